// round 7
// baseline (speedup 1.0000x reference)
#include <cuda_runtime.h>
#include <cuda_fp16.h>
#include <cstdint>

typedef unsigned int u32;
typedef unsigned long long u64;

#define NB 4
#define NC 256
#define NHW 4096

// ---------------- device scratch ----------------
__device__ __align__(16) __half g_CM_hi[27][64][256];
__device__ __align__(16) __half g_CM_lo[27][64][256];
__device__ float g_pp_sum[27][4][8][64];
__device__ float g_pp_max[27][4][8][64];
__device__ float g_o[9][4][256];
__device__ __align__(16) __half g_xT_hi[12u * 4096u * 256u];
__device__ __align__(16) __half g_xT_lo[12u * 4096u * 256u];
__device__ __align__(16) __half g_W5[4 * 2 * 3 * 2 * 128 * 256];

// ---------------- helpers ----------------
static __device__ __forceinline__ u32 smem_u32(const void* p) {
    return (u32)__cvta_generic_to_shared(p);
}
static __device__ __forceinline__ void cp16(u32 d, const void* s) {
    asm volatile("cp.async.cg.shared.global [%0], [%1], 16;" :: "r"(d), "l"(s));
}
#define CP_COMMIT() asm volatile("cp.async.commit_group;" ::: "memory")
#define CP_WAIT1()  asm volatile("cp.async.wait_group 1;" ::: "memory")
#define CP_WAIT0()  asm volatile("cp.async.wait_group 0;" ::: "memory")

static __device__ __forceinline__ void ldsm4(u32* r, u32 a) {
    asm volatile("ldmatrix.sync.aligned.m8n8.x4.shared.b16 {%0,%1,%2,%3}, [%4];"
                 : "=r"(r[0]), "=r"(r[1]), "=r"(r[2]), "=r"(r[3]) : "r"(a));
}
static __device__ __forceinline__ void mma16816(float* d, const u32* a, const u32* b) {
    asm volatile(
        "mma.sync.aligned.m16n8k16.row.col.f32.f16.f16.f32 "
        "{%0,%1,%2,%3},{%4,%5,%6,%7},{%8,%9},{%0,%1,%2,%3};"
        : "+f"(d[0]), "+f"(d[1]), "+f"(d[2]), "+f"(d[3])
        : "r"(a[0]), "r"(a[1]), "r"(a[2]), "r"(a[3]), "r"(b[0]), "r"(b[1]));
}
static __device__ __forceinline__ void split_h(float v, __half& h, __half& l) {
    h = __float2half_rn(v);
    l = __float2half_rn(v - __half2float(h));
}

// smem layout (bytes). Rows: 256 fp16 = 512B + 16B pad = 528B
#define ROWB   528
#define SA_HI  0
#define SA_LO  67584           // 128*528
#define SM_B   135168
#define BBUF   33792           // 64 rows * 528 (one plane)
#define SMEMSZ 202752          // A + 2 plane buffers

// ============================================================================
// K0: transpose + fp16-split x -> g_xT_hi/lo [src*4+b][hw][cin]
// ============================================================================
__global__ void k0_split(const float* __restrict__ xt, const float* __restrict__ xb,
                         const float* __restrict__ xm) {
    int sb = blockIdx.x;
    int src = sb >> 2, b = sb & 3;
    const float* xs = (src == 0) ? xt : (src == 1) ? xb : xm;
    int cin0 = blockIdx.y * 32, hw0 = blockIdx.z * 256;
    __shared__ float s[32][257];
    const float* base = xs + ((size_t)b * NC + cin0) * NHW + hw0;
    for (int i = threadIdx.x; i < 32 * 256; i += 256) {
        int r = i >> 8, c = i & 255;
        s[r][c] = base[(size_t)r * NHW + c];
    }
    __syncthreads();
    int t = threadIdx.x;
    u32 hb[16], lb[16];
#pragma unroll
    for (int m = 0; m < 16; m++) {
        __half h0, l0, h1, l1;
        split_h(s[2 * m][t], h0, l0);
        split_h(s[2 * m + 1][t], h1, l1);
        hb[m] = (u32)__half_as_ushort(h0) | ((u32)__half_as_ushort(h1) << 16);
        lb[m] = (u32)__half_as_ushort(l0) | ((u32)__half_as_ushort(l1) << 16);
    }
    size_t ro = ((size_t)sb * 4096 + hw0 + t) * 256 + cin0;
    uint4* dh = (uint4*)&g_xT_hi[ro];
    uint4* dl = (uint4*)&g_xT_lo[ro];
#pragma unroll
    for (int q = 0; q < 4; q++) {
        dh[q] = make_uint4(hb[4 * q], hb[4 * q + 1], hb[4 * q + 2], hb[4 * q + 3]);
        dl[q] = make_uint4(lb[4 * q], lb[4 * q + 1], lb[4 * q + 2], lb[4 * q + 3]);
    }
}

// ============================================================================
// K1: combined matrices Wred[e]@Wqkv[w] -> split fp16 g_CM_hi/lo[combo][cp][cin]
// ============================================================================
__global__ void k1_cm(const float* __restrict__ Wqkv, const float* __restrict__ Wred) {
    int combo = blockIdx.x;
    int e = combo / 3, r = combo % 3;
    int ii = e / 3, jj = e % 3;
    int w = (r == 0) ? 3 * jj : (r == 1) ? (3 * ii + 1) : (3 * jj + 2);
    int cc0 = blockIdx.y * 64;

    __shared__ float sA[64][65];
    __shared__ float sB[64][65];

    int tx = threadIdx.x & 15, ty = threadIdx.x >> 4;
    float acc[4][4] = {};

    const float* A = Wred + (size_t)e * 64 * 256;
    const float* Bm = Wqkv + (size_t)w * 65536;

    for (int k0 = 0; k0 < 256; k0 += 64) {
        for (int idx = threadIdx.x; idx < 4096; idx += 256) {
            int rr = idx >> 6, cl = idx & 63;
            sA[rr][cl] = A[rr * 256 + k0 + cl];
            sB[rr][cl] = Bm[(k0 + rr) * 256 + cc0 + cl];
        }
        __syncthreads();
#pragma unroll
        for (int kk = 0; kk < 64; kk++) {
            float av[4], bv[4];
#pragma unroll
            for (int u = 0; u < 4; u++) av[u] = sA[ty * 4 + u][kk];
#pragma unroll
            for (int v = 0; v < 4; v++) bv[v] = sB[kk][tx * 4 + v];
#pragma unroll
            for (int u = 0; u < 4; u++)
#pragma unroll
                for (int v = 0; v < 4; v++) acc[u][v] = fmaf(av[u], bv[v], acc[u][v]);
        }
        __syncthreads();
    }
#pragma unroll
    for (int u = 0; u < 4; u++)
#pragma unroll
        for (int v = 0; v < 4; v++) {
            __half h, l;
            split_h(acc[u][v], h, l);
            g_CM_hi[combo][ty * 4 + u][cc0 + tx * 4 + v] = h;
            g_CM_lo[combo][ty * 4 + u][cc0 + tx * 4 + v] = l;
        }
}

// ---- plane loader: 64 hw rows of one fp16 plane into padded smem ----
static __device__ __forceinline__ void load_plane64(
    u32 dst, const __half* X, int hw0, int tid) {
#pragma unroll
    for (int i = 0; i < 8; i++) {
        int f = tid + i * 256;
        int row = f >> 5, c = f & 31;
        cp16(dst + row * ROWB + c * 16, X + (size_t)(hw0 + row) * 256 + c * 8);
    }
}

// ============================================================================
// K2: HMMA reduced projection (fp16 2-term) + relu + pool.
//     grid (15, 4 b, 8 z of 512 hw), block 256 (4m x 2n warps).
//     8 steps of 64 hw, double-buffered B (hi plane only).
// ============================================================================
__global__ void __launch_bounds__(256, 1)
k2_mma() {
    extern __shared__ __align__(16) char sm[];
    u32 smb = smem_u32(sm);

    int tid = threadIdx.x, wid = tid >> 5, lane = tid & 31;
    int src = blockIdx.x / 5, mt = blockIdx.x % 5;
    int b = blockIdx.y, z = blockIdx.z;

    int list[9];
    int n = 0;
    for (int combo = 0; combo < 27; combo++) {
        int e = combo / 3, r = combo % 3;
        int sc = (r == 1) ? e / 3 : e % 3;
        if (sc == src) list[n++] = combo;
    }
    int c0 = list[2 * mt];
    bool has1 = (2 * mt + 1) < 9;
    int c1 = has1 ? list[2 * mt + 1] : c0;

    const __half* XH = g_xT_hi + (size_t)(src * 4 + b) * 4096 * 256;

#pragma unroll
    for (int i = 0; i < 16; i++) {
        int f = tid + i * 256;
        int row = f >> 5, c = f & 31;
        int cb = (row < 64) ? c0 : c1;
        size_t so = ((size_t)cb * 64 + (row & 63)) * 256 + c * 8;
        cp16(smb + SA_HI + row * ROWB + c * 16, &g_CM_hi[0][0][0] + so);
        cp16(smb + SA_LO + row * ROWB + c * 16, &g_CM_lo[0][0][0] + so);
    }
    CP_COMMIT();
    load_plane64(smb + SM_B, XH, z * 512, tid);
    CP_COMMIT();

    int mwarp = wid >> 1, nwarp = wid & 1;
    int R0 = mwarp * 32;
    int H = nwarp * 32;

    u32 aoff = (u32)(R0 + (lane & 15)) * ROWB + (lane >> 4) * 16;
    u32 aHi = smb + SA_HI + aoff;
    u32 aLo = smb + SA_LO + aoff;
    u32 boff = (u32)(H + (lane & 7) + ((lane >= 16) ? 8 : 0)) * ROWB + ((lane & 8) ? 16 : 0);

    float psum[2][2] = {}, pmax[2][2] = {};

    for (int step = 0; step < 8; step++) {
        if (step < 7) {
            load_plane64(smb + SM_B + ((step + 1) & 1) * BBUF, XH, z * 512 + (step + 1) * 64, tid);
            CP_COMMIT();
            CP_WAIT1();
        } else {
            CP_WAIT0();
        }
        __syncthreads();

        u32 bHi = smb + SM_B + (step & 1) * BBUF + boff;

        float acc[2][4][4] = {};
#pragma unroll
        for (int kk = 0; kk < 16; kk++) {
            u32 kb = kk * 32;
            u32 ah0[4], ah1[4], al0[4], al1[4], bh0[4], bh1[4];
            ldsm4(ah0, aHi + kb);
            ldsm4(ah1, aHi + 16 * ROWB + kb);
            ldsm4(al0, aLo + kb);
            ldsm4(al1, aLo + 16 * ROWB + kb);
            ldsm4(bh0, bHi + kb);
            ldsm4(bh1, bHi + 16 * ROWB + kb);
#pragma unroll
            for (int m = 0; m < 2; m++) {
                const u32* ah = m ? ah1 : ah0;
                const u32* al = m ? al1 : al0;
                mma16816(acc[m][0], ah, bh0);
                mma16816(acc[m][0], al, bh0);
                mma16816(acc[m][1], ah, bh0 + 2);
                mma16816(acc[m][1], al, bh0 + 2);
                mma16816(acc[m][2], ah, bh1);
                mma16816(acc[m][2], al, bh1);
                mma16816(acc[m][3], ah, bh1 + 2);
                mma16816(acc[m][3], al, bh1 + 2);
            }
        }
#pragma unroll
        for (int m = 0; m < 2; m++)
#pragma unroll
            for (int nt = 0; nt < 4; nt++) {
                float r0 = fmaxf(acc[m][nt][0], 0.f), r1 = fmaxf(acc[m][nt][1], 0.f);
                float r2 = fmaxf(acc[m][nt][2], 0.f), r3 = fmaxf(acc[m][nt][3], 0.f);
                psum[m][0] += r0 + r1;
                psum[m][1] += r2 + r3;
                pmax[m][0] = fmaxf(pmax[m][0], fmaxf(r0, r1));
                pmax[m][1] = fmaxf(pmax[m][1], fmaxf(r2, r3));
            }
        __syncthreads();
    }

#pragma unroll
    for (int m = 0; m < 2; m++)
#pragma unroll
        for (int h = 0; h < 2; h++) {
#pragma unroll
            for (int off = 1; off <= 2; off <<= 1) {
                psum[m][h] += __shfl_xor_sync(0xffffffffu, psum[m][h], off);
                pmax[m][h] = fmaxf(pmax[m][h], __shfl_xor_sync(0xffffffffu, pmax[m][h], off));
            }
        }

    float* ps = (float*)(sm + SM_B);
    float* pm = ps + 256;
    if ((lane & 3) == 0) {
        int g = lane >> 2;
#pragma unroll
        for (int m = 0; m < 2; m++)
#pragma unroll
            for (int h = 0; h < 2; h++) {
                int row = R0 + m * 16 + h * 8 + g;
                ps[row * 2 + nwarp] = psum[m][h];
                pm[row * 2 + nwarp] = pmax[m][h];
            }
    }
    __syncthreads();
    if (tid < 128) {
        float s = ps[tid * 2] + ps[tid * 2 + 1];
        float m = fmaxf(pm[tid * 2], pm[tid * 2 + 1]);
        if (tid < 64 || has1) {
            int cb = (tid < 64) ? c0 : c1;
            g_pp_sum[cb][b][z][tid & 63] = s;
            g_pp_max[cb][b][z][tid & 63] = m;
        }
    }
}

// ============================================================================
// K3: channel-attention math per (e, b). grid (9,4), block 256.
// ============================================================================
__global__ void k3_attn(const float* __restrict__ Wrec) {
    int e = blockIdx.x, b = blockIdx.y;
    __shared__ float fS[64], gS[64], hS[64], vout[64];
    __shared__ float redA[4][64], redB[4][64];
    int tid = threadIdx.x;
    int j = tid & 63, p = tid >> 6;

    if (p < 3) {
        float s = 0.f, m = 0.f;
#pragma unroll
        for (int ch = 0; ch < 8; ch++) {
            s += g_pp_sum[e * 3 + p][b][ch][j];
            m = fmaxf(m, g_pp_max[e * 3 + p][b][ch][j]);
        }
        float val = s * (1.f / 4096.f) + m;
        if (p == 0) gS[j] = val;
        else if (p == 1) fS[j] = val;
        else hS[j] = val;
    }
    __syncthreads();

    float gj = gS[j];
    float lmax = -1e30f;
#pragma unroll
    for (int i = p * 16; i < p * 16 + 16; i++) lmax = fmaxf(lmax, fS[i] * gj);
    redA[p][j] = lmax;
    __syncthreads();
    float mx = fmaxf(fmaxf(redA[0][j], redA[1][j]), fmaxf(redA[2][j], redA[3][j]));
    __syncthreads();
    float den = 0.f, num = 0.f;
#pragma unroll
    for (int i = p * 16; i < p * 16 + 16; i++) {
        float ev = expf(fS[i] * gj - mx);
        den += ev;
        num += hS[i] * ev;
    }
    redA[p][j] = den;
    redB[p][j] = num;
    __syncthreads();
    if (p == 0)
        vout[j] = (redB[0][j] + redB[1][j] + redB[2][j] + redB[3][j]) /
                  (redA[0][j] + redA[1][j] + redA[2][j] + redA[3][j]);
    __syncthreads();

    const float* wr = Wrec + ((size_t)e * 256 + tid) * 64;
    float acc = 0.f;
#pragma unroll 8
    for (int q = 0; q < 64; q++) acc = fmaf(vout[q], wr[q], acc);
    g_o[e][b][tid] = 1.f / (1.f + expf(-acc));
}

// ============================================================================
// K4: build gated split weights g_W5[b][ct][s][hi/lo][128][256]
// ============================================================================
__global__ void k4_w5(const float* __restrict__ Wqkv) {
    int b = blockIdx.x, ct = blockIdx.y, s = blockIdx.z;
    __shared__ float sA[128], sB[128];
    if (threadIdx.x < 128) {
        int c = ct * 128 + threadIdx.x;
        sA[threadIdx.x] = g_o[s][b][c] + g_o[s + 3][b][c] + g_o[s + 6][b][c];
        sB[threadIdx.x] = g_o[3 * s][b][c] + g_o[3 * s + 1][b][c] + g_o[3 * s + 2][b][c];
    }
    __syncthreads();
    const float* Wq = Wqkv + (size_t)(3 * s) * 65536 + (size_t)ct * 128 * 256;
    const float* Wk = Wq + 65536;
    const float* Wv = Wk + 65536;
    size_t base = (((size_t)(b * 2 + ct) * 3 + s) * 2) * 128 * 256;
    for (int i = threadIdx.x; i < 128 * 256; i += 256) {
        int row = i >> 8, cin = i & 255;
        float w = sA[row] * (Wq[row * 256 + cin] + Wv[row * 256 + cin])
                + sB[row] * Wk[row * 256 + cin];
        __half h, l;
        split_h(w, h, l);
        g_W5[base + i] = h;
        g_W5[base + 128 * 256 + i] = l;
    }
}

// ============================================================================
// K5: HMMA output GEMM (fp16 3-term) with split-wait pipeline.
//     grid (2 ct, 4 b, 32 hz of 128 hw), block 256 (4m x 2n warps).
//     Per step: hi-terms computed while Blo in flight; Bhi(next) prefetched
//     during lo-term compute; A(s+1)+Blo(next) issued after lo-term.
// ============================================================================
__global__ void __launch_bounds__(256, 1)
k5_mma(float* __restrict__ out) {
    extern __shared__ __align__(16) char sm[];
    u32 smb = smem_u32(sm);

    int tid = threadIdx.x, wid = tid >> 5, lane = tid & 31;
    int ct = blockIdx.x, b = blockIdx.y, hz = blockIdx.z;

    int mwarp = wid >> 1, nwarp = wid & 1;
    int R0 = mwarp * 32;
    int H = nwarp * 32;

    u32 aoff = (u32)(R0 + (lane & 15)) * ROWB + (lane >> 4) * 16;
    u32 aHi = smb + SA_HI + aoff;
    u32 aLo = smb + SA_LO + aoff;
    u32 boff = (u32)(H + (lane & 7) + ((lane >= 16) ? 8 : 0)) * ROWB + ((lane & 8) ? 16 : 0);
    u32 bHi = smb + SM_B + boff;
    u32 bLo = bHi + BBUF;

    float acc[2][2][4][4] = {};   // [step][m][nt][4]

    // prologue: A(0), Bhi(0,0), Blo(0,0) as 3 groups
    {
        const __half* WA = g_W5 + (((size_t)(b * 2 + ct) * 3) * 2) * 128 * 256;
#pragma unroll
        for (int i = 0; i < 16; i++) {
            int f = tid + i * 256;
            int row = f >> 5, c = f & 31;
            size_t so = (size_t)row * 256 + c * 8;
            cp16(smb + SA_HI + row * ROWB + c * 16, WA + so);
            cp16(smb + SA_LO + row * ROWB + c * 16, WA + 128 * 256 + so);
        }
        CP_COMMIT();
        load_plane64(smb + SM_B, g_xT_hi + (size_t)b * 4096 * 256, hz * 128, tid);
        CP_COMMIT();
        load_plane64(smb + SM_B + BBUF, g_xT_lo + (size_t)b * 4096 * 256, hz * 128, tid);
        CP_COMMIT();
    }

    for (int s = 0; s < 3; s++) {
        const __half* XH = g_xT_hi + (size_t)(s * 4 + b) * 4096 * 256;
        const __half* XL = g_xT_lo + (size_t)(s * 4 + b) * 4096 * 256;
        const __half* XHn = g_xT_hi + (size_t)(((s + 1) % 3) * 4 + b) * 4096 * 256;
        const __half* XLn = g_xT_lo + (size_t)(((s + 1) % 3) * 4 + b) * 4096 * 256;

#pragma unroll
        for (int step = 0; step < 2; step++) {
            CP_WAIT1();            // A + Bhi(cur) ready; Blo(cur) may be in flight
            __syncthreads();

            // hi terms: Ah*Bh + Al*Bh
#pragma unroll
            for (int kk = 0; kk < 16; kk++) {
                u32 kb = kk * 32;
                u32 ah0[4], ah1[4], al0[4], al1[4], bh0[4], bh1[4];
                ldsm4(ah0, aHi + kb);
                ldsm4(ah1, aHi + 16 * ROWB + kb);
                ldsm4(al0, aLo + kb);
                ldsm4(al1, aLo + 16 * ROWB + kb);
                ldsm4(bh0, bHi + kb);
                ldsm4(bh1, bHi + 16 * ROWB + kb);
#pragma unroll
                for (int m = 0; m < 2; m++) {
                    const u32* ah = m ? ah1 : ah0;
                    const u32* al = m ? al1 : al0;
                    mma16816(acc[step][m][0], ah, bh0);
                    mma16816(acc[step][m][0], al, bh0);
                    mma16816(acc[step][m][1], ah, bh0 + 2);
                    mma16816(acc[step][m][1], al, bh0 + 2);
                    mma16816(acc[step][m][2], ah, bh1);
                    mma16816(acc[step][m][2], al, bh1);
                    mma16816(acc[step][m][3], ah, bh1 + 2);
                    mma16816(acc[step][m][3], al, bh1 + 2);
                }
            }
            __syncthreads();       // all warps done reading Bhi buffer

            // prefetch next Bhi (into the now-free hi buffer)
            if (step == 0) {
                load_plane64(smb + SM_B, XH, hz * 128 + 64, tid);
                CP_COMMIT();
            } else if (s < 2) {
                load_plane64(smb + SM_B, XHn, hz * 128, tid);
                CP_COMMIT();
            }

            CP_WAIT1();            // Blo(cur) ready; next Bhi in flight
            __syncthreads();

            // lo term: Ah*Bl
#pragma unroll
            for (int kk = 0; kk < 16; kk++) {
                u32 kb = kk * 32;
                u32 ah0[4], ah1[4], bl0[4], bl1[4];
                ldsm4(ah0, aHi + kb);
                ldsm4(ah1, aHi + 16 * ROWB + kb);
                ldsm4(bl0, bLo + kb);
                ldsm4(bl1, bLo + 16 * ROWB + kb);
#pragma unroll
                for (int m = 0; m < 2; m++) {
                    const u32* ah = m ? ah1 : ah0;
                    mma16816(acc[step][m][0], ah, bl0);
                    mma16816(acc[step][m][1], ah, bl0 + 2);
                    mma16816(acc[step][m][2], ah, bl1);
                    mma16816(acc[step][m][3], ah, bl1 + 2);
                }
            }
            __syncthreads();       // done reading Blo + A (for s-boundary reuse)

            // issue next Blo (+ next A at s boundary)
            if (step == 0) {
                load_plane64(smb + SM_B + BBUF, XL, hz * 128 + 64, tid);
                CP_COMMIT();
            } else if (s < 2) {
                const __half* WA = g_W5 + (((size_t)(b * 2 + ct) * 3 + (s + 1)) * 2) * 128 * 256;
#pragma unroll
                for (int i = 0; i < 16; i++) {
                    int f = tid + i * 256;
                    int row = f >> 5, c = f & 31;
                    size_t so = (size_t)row * 256 + c * 8;
                    cp16(smb + SA_HI + row * ROWB + c * 16, WA + so);
                    cp16(smb + SA_LO + row * ROWB + c * 16, WA + 128 * 256 + so);
                }
                CP_COMMIT();
                load_plane64(smb + SM_B + BBUF, XLn, hz * 128, tid);
                CP_COMMIT();
            }
        }
    }

    // store
    int g = lane >> 2, t = lane & 3;
#pragma unroll
    for (int step = 0; step < 2; step++)
#pragma unroll
        for (int m = 0; m < 2; m++)
#pragma unroll
            for (int nt = 0; nt < 4; nt++) {
                int ch = ct * 128 + R0 + m * 16 + g;
                int col = hz * 128 + step * 64 + H + nt * 8 + 2 * t;
                float2* p0 = (float2*)(out + ((size_t)b * NC + ch) * NHW + col);
                float2* p1 = (float2*)(out + ((size_t)b * NC + ch + 8) * NHW + col);
                *p0 = make_float2(acc[step][m][nt][0], acc[step][m][nt][1]);
                *p1 = make_float2(acc[step][m][nt][2], acc[step][m][nt][3]);
            }
}

// ============================================================================
extern "C" void kernel_launch(void* const* d_in, const int* in_sizes, int n_in,
                              void* d_out, int out_size) {
    (void)in_sizes; (void)n_in; (void)out_size;
    const float* t    = (const float*)d_in[0];
    const float* bb   = (const float*)d_in[1];
    const float* mm   = (const float*)d_in[2];
    const float* Wqkv = (const float*)d_in[3];
    const float* Wred = (const float*)d_in[4];
    const float* Wrec = (const float*)d_in[5];
    float* out = (float*)d_out;

    cudaFuncSetAttribute(k2_mma, cudaFuncAttributeMaxDynamicSharedMemorySize, SMEMSZ);
    cudaFuncSetAttribute(k5_mma, cudaFuncAttributeMaxDynamicSharedMemorySize, SMEMSZ);

    k0_split<<<dim3(12, 8, 16), 256>>>(t, bb, mm);
    k1_cm<<<dim3(27, 4), 256>>>(Wqkv, Wred);
    k2_mma<<<dim3(15, 4, 8), 256, SMEMSZ>>>();
    k3_attn<<<dim3(9, 4), 256>>>(Wrec);
    k4_w5<<<dim3(4, 2, 3), 256>>>(Wqkv);
    k5_mma<<<dim3(2, 4, 32), 256, SMEMSZ>>>(out);
}

// round 9
// speedup vs baseline: 1.4219x; 1.4219x over previous
#include <cuda_runtime.h>
#include <cuda_fp16.h>
#include <cstdint>

typedef unsigned int u32;
typedef unsigned long long u64;

#define NB 4
#define NC 256
#define NHW 4096

// ---------------- device scratch ----------------
__device__ __align__(16) __half g_CM_hi[27][64][256];   // combined matrices (fp16)
__device__ float g_pp_sum[27][4][8][64];
__device__ float g_pp_max[27][4][8][64];
__device__ float g_o[9][4][256];
// x transposed, fp16 hi plane only: [src*4+b][hw 4096][cin 256]
__device__ __align__(16) __half g_xT_hi[12u * 4096u * 256u];
// gated output weights, split hi/lo: [b][ct][s][hi/lo][128][256]
__device__ __align__(16) __half g_W5[4 * 2 * 3 * 2 * 128 * 256];

// ---------------- helpers ----------------
static __device__ __forceinline__ u32 smem_u32(const void* p) {
    return (u32)__cvta_generic_to_shared(p);
}
static __device__ __forceinline__ void cp16(u32 d, const void* s) {
    asm volatile("cp.async.cg.shared.global [%0], [%1], 16;" :: "r"(d), "l"(s));
}
#define CP_COMMIT() asm volatile("cp.async.commit_group;" ::: "memory")
#define CP_WAIT1()  asm volatile("cp.async.wait_group 1;" ::: "memory")
#define CP_WAIT0()  asm volatile("cp.async.wait_group 0;" ::: "memory")

static __device__ __forceinline__ void ldsm4(u32* r, u32 a) {
    asm volatile("ldmatrix.sync.aligned.m8n8.x4.shared.b16 {%0,%1,%2,%3}, [%4];"
                 : "=r"(r[0]), "=r"(r[1]), "=r"(r[2]), "=r"(r[3]) : "r"(a));
}
static __device__ __forceinline__ void mma16816(float* d, const u32* a, const u32* b) {
    asm volatile(
        "mma.sync.aligned.m16n8k16.row.col.f32.f16.f16.f32 "
        "{%0,%1,%2,%3},{%4,%5,%6,%7},{%8,%9},{%0,%1,%2,%3};"
        : "+f"(d[0]), "+f"(d[1]), "+f"(d[2]), "+f"(d[3])
        : "r"(a[0]), "r"(a[1]), "r"(a[2]), "r"(a[3]), "r"(b[0]), "r"(b[1]));
}
static __device__ __forceinline__ void split_h(float v, __half& h, __half& l) {
    h = __float2half_rn(v);
    l = __float2half_rn(v - __half2float(h));
}

// smem layout (bytes). Rows: 256 fp16 = 512B + 16B pad = 528B
#define ROWB     528
#define BBUF     33792            // 64 rows * 528 (one plane)
// k2: A-hi [128 rows] + 2 B buffers
#define K2_SMB   67584            // 128*528
#define K2_SMEM  (K2_SMB + 2 * BBUF)     // 135168
// k5: A-hi + A-lo [128 rows each] + 2 B buffers
#define SA_LO    67584
#define K5_SMB   135168
#define K5_SMEM  (K5_SMB + 2 * BBUF)     // 202752

// ============================================================================
// K0: transpose + fp16 x -> g_xT_hi [src*4+b][hw][cin]
// ============================================================================
__global__ void k0_split(const float* __restrict__ xt, const float* __restrict__ xb,
                         const float* __restrict__ xm) {
    int sb = blockIdx.x;
    int src = sb >> 2, b = sb & 3;
    const float* xs = (src == 0) ? xt : (src == 1) ? xb : xm;
    int cin0 = blockIdx.y * 32, hw0 = blockIdx.z * 256;
    __shared__ float s[32][257];
    const float* base = xs + ((size_t)b * NC + cin0) * NHW + hw0;
    for (int i = threadIdx.x; i < 32 * 256; i += 256) {
        int r = i >> 8, c = i & 255;
        s[r][c] = base[(size_t)r * NHW + c];
    }
    __syncthreads();
    int t = threadIdx.x;
    u32 hb[16];
#pragma unroll
    for (int m = 0; m < 16; m++) {
        __half h0 = __float2half_rn(s[2 * m][t]);
        __half h1 = __float2half_rn(s[2 * m + 1][t]);
        hb[m] = (u32)__half_as_ushort(h0) | ((u32)__half_as_ushort(h1) << 16);
    }
    size_t ro = ((size_t)sb * 4096 + hw0 + t) * 256 + cin0;
    uint4* dh = (uint4*)&g_xT_hi[ro];
#pragma unroll
    for (int q = 0; q < 4; q++)
        dh[q] = make_uint4(hb[4 * q], hb[4 * q + 1], hb[4 * q + 2], hb[4 * q + 3]);
}

// ============================================================================
// K1: combined matrices Wred[e]@Wqkv[w] -> fp16 g_CM_hi[combo][cp][cin]
// ============================================================================
__global__ void k1_cm(const float* __restrict__ Wqkv, const float* __restrict__ Wred) {
    int combo = blockIdx.x;
    int e = combo / 3, r = combo % 3;
    int ii = e / 3, jj = e % 3;
    int w = (r == 0) ? 3 * jj : (r == 1) ? (3 * ii + 1) : (3 * jj + 2);
    int cc0 = blockIdx.y * 64;

    __shared__ float sA[64][65];
    __shared__ float sB[64][65];

    int tx = threadIdx.x & 15, ty = threadIdx.x >> 4;
    float acc[4][4] = {};

    const float* A = Wred + (size_t)e * 64 * 256;
    const float* Bm = Wqkv + (size_t)w * 65536;

    for (int k0 = 0; k0 < 256; k0 += 64) {
        for (int idx = threadIdx.x; idx < 4096; idx += 256) {
            int rr = idx >> 6, cl = idx & 63;
            sA[rr][cl] = A[rr * 256 + k0 + cl];
            sB[rr][cl] = Bm[(k0 + rr) * 256 + cc0 + cl];
        }
        __syncthreads();
#pragma unroll
        for (int kk = 0; kk < 64; kk++) {
            float av[4], bv[4];
#pragma unroll
            for (int u = 0; u < 4; u++) av[u] = sA[ty * 4 + u][kk];
#pragma unroll
            for (int v = 0; v < 4; v++) bv[v] = sB[kk][tx * 4 + v];
#pragma unroll
            for (int u = 0; u < 4; u++)
#pragma unroll
                for (int v = 0; v < 4; v++) acc[u][v] = fmaf(av[u], bv[v], acc[u][v]);
        }
        __syncthreads();
    }
#pragma unroll
    for (int u = 0; u < 4; u++)
#pragma unroll
        for (int v = 0; v < 4; v++)
            g_CM_hi[combo][ty * 4 + u][cc0 + tx * 4 + v] = __float2half_rn(acc[u][v]);
}

// ---- plane loader: 64 hw rows of the fp16 hi plane into padded smem ----
static __device__ __forceinline__ void load_plane64(
    u32 dst, const __half* X, int hw0, int tid) {
#pragma unroll
    for (int i = 0; i < 8; i++) {
        int f = tid + i * 256;
        int row = f >> 5, c = f & 31;
        cp16(dst + row * ROWB + c * 16, X + (size_t)(hw0 + row) * 256 + c * 8);
    }
}

// ============================================================================
// K2: HMMA reduced projection (fp16 1-term) + relu + pool.
//     grid (15, 4 b, 8 z of 512 hw), block 256 (4m x 2n warps).
//     8 steps of 64 hw, double-buffered B.
// ============================================================================
__global__ void __launch_bounds__(256, 1)
k2_mma() {
    extern __shared__ __align__(16) char sm[];
    u32 smb = smem_u32(sm);

    int tid = threadIdx.x, wid = tid >> 5, lane = tid & 31;
    int src = blockIdx.x / 5, mt = blockIdx.x % 5;
    int b = blockIdx.y, z = blockIdx.z;

    int list[9];
    int n = 0;
    for (int combo = 0; combo < 27; combo++) {
        int e = combo / 3, r = combo % 3;
        int sc = (r == 1) ? e / 3 : e % 3;
        if (sc == src) list[n++] = combo;
    }
    int c0 = list[2 * mt];
    bool has1 = (2 * mt + 1) < 9;
    int c1 = has1 ? list[2 * mt + 1] : c0;

    const __half* XH = g_xT_hi + (size_t)(src * 4 + b) * 4096 * 256;

    // A load: 128 rows x 32 chunks (hi plane) — 16 iterations REQUIRED
#pragma unroll
    for (int i = 0; i < 16; i++) {
        int f = tid + i * 256;          // 0..4095
        int row = f >> 5, c = f & 31;   // rows 0..127
        int cb = (row < 64) ? c0 : c1;
        size_t so = ((size_t)cb * 64 + (row & 63)) * 256 + c * 8;
        cp16(smb + row * ROWB + c * 16, &g_CM_hi[0][0][0] + so);
    }
    CP_COMMIT();
    load_plane64(smb + K2_SMB, XH, z * 512, tid);
    CP_COMMIT();

    int mwarp = wid >> 1, nwarp = wid & 1;
    int R0 = mwarp * 32;
    int H = nwarp * 32;

    u32 aoff = (u32)(R0 + (lane & 15)) * ROWB + (lane >> 4) * 16;
    u32 aHi = smb + aoff;
    u32 boff = (u32)(H + (lane & 7) + ((lane >= 16) ? 8 : 0)) * ROWB + ((lane & 8) ? 16 : 0);

    float psum[2][2] = {}, pmax[2][2] = {};

    for (int step = 0; step < 8; step++) {
        if (step < 7) {
            load_plane64(smb + K2_SMB + ((step + 1) & 1) * BBUF, XH, z * 512 + (step + 1) * 64, tid);
            CP_COMMIT();
            CP_WAIT1();
        } else {
            CP_WAIT0();
        }
        __syncthreads();

        u32 bHi = smb + K2_SMB + (step & 1) * BBUF + boff;

        float acc[2][4][4] = {};
#pragma unroll
        for (int kk = 0; kk < 16; kk++) {
            u32 kb = kk * 32;
            u32 ah0[4], ah1[4], bh0[4], bh1[4];
            ldsm4(ah0, aHi + kb);
            ldsm4(ah1, aHi + 16 * ROWB + kb);
            ldsm4(bh0, bHi + kb);
            ldsm4(bh1, bHi + 16 * ROWB + kb);
#pragma unroll
            for (int m = 0; m < 2; m++) {
                const u32* ah = m ? ah1 : ah0;
                mma16816(acc[m][0], ah, bh0);
                mma16816(acc[m][1], ah, bh0 + 2);
                mma16816(acc[m][2], ah, bh1);
                mma16816(acc[m][3], ah, bh1 + 2);
            }
        }
#pragma unroll
        for (int m = 0; m < 2; m++)
#pragma unroll
            for (int nt = 0; nt < 4; nt++) {
                float r0 = fmaxf(acc[m][nt][0], 0.f), r1 = fmaxf(acc[m][nt][1], 0.f);
                float r2 = fmaxf(acc[m][nt][2], 0.f), r3 = fmaxf(acc[m][nt][3], 0.f);
                psum[m][0] += r0 + r1;
                psum[m][1] += r2 + r3;
                pmax[m][0] = fmaxf(pmax[m][0], fmaxf(r0, r1));
                pmax[m][1] = fmaxf(pmax[m][1], fmaxf(r2, r3));
            }
        __syncthreads();
    }

#pragma unroll
    for (int m = 0; m < 2; m++)
#pragma unroll
        for (int h = 0; h < 2; h++) {
#pragma unroll
            for (int off = 1; off <= 2; off <<= 1) {
                psum[m][h] += __shfl_xor_sync(0xffffffffu, psum[m][h], off);
                pmax[m][h] = fmaxf(pmax[m][h], __shfl_xor_sync(0xffffffffu, pmax[m][h], off));
            }
        }

    float* ps = (float*)(sm + K2_SMB);
    float* pm = ps + 256;
    if ((lane & 3) == 0) {
        int g = lane >> 2;
#pragma unroll
        for (int m = 0; m < 2; m++)
#pragma unroll
            for (int h = 0; h < 2; h++) {
                int row = R0 + m * 16 + h * 8 + g;
                ps[row * 2 + nwarp] = psum[m][h];
                pm[row * 2 + nwarp] = pmax[m][h];
            }
    }
    __syncthreads();
    if (tid < 128) {
        float s = ps[tid * 2] + ps[tid * 2 + 1];
        float m = fmaxf(pm[tid * 2], pm[tid * 2 + 1]);
        if (tid < 64 || has1) {
            int cb = (tid < 64) ? c0 : c1;
            g_pp_sum[cb][b][z][tid & 63] = s;
            g_pp_max[cb][b][z][tid & 63] = m;
        }
    }
}

// ============================================================================
// K3: channel-attention math per (e, b). grid (9,4), block 256.
// ============================================================================
__global__ void k3_attn(const float* __restrict__ Wrec) {
    int e = blockIdx.x, b = blockIdx.y;
    __shared__ float fS[64], gS[64], hS[64], vout[64];
    __shared__ float redA[4][64], redB[4][64];
    int tid = threadIdx.x;
    int j = tid & 63, p = tid >> 6;

    if (p < 3) {
        float s = 0.f, m = 0.f;
#pragma unroll
        for (int ch = 0; ch < 8; ch++) {
            s += g_pp_sum[e * 3 + p][b][ch][j];
            m = fmaxf(m, g_pp_max[e * 3 + p][b][ch][j]);
        }
        float val = s * (1.f / 4096.f) + m;
        if (p == 0) gS[j] = val;
        else if (p == 1) fS[j] = val;
        else hS[j] = val;
    }
    __syncthreads();

    float gj = gS[j];
    float lmax = -1e30f;
#pragma unroll
    for (int i = p * 16; i < p * 16 + 16; i++) lmax = fmaxf(lmax, fS[i] * gj);
    redA[p][j] = lmax;
    __syncthreads();
    float mx = fmaxf(fmaxf(redA[0][j], redA[1][j]), fmaxf(redA[2][j], redA[3][j]));
    __syncthreads();
    float den = 0.f, num = 0.f;
#pragma unroll
    for (int i = p * 16; i < p * 16 + 16; i++) {
        float ev = expf(fS[i] * gj - mx);
        den += ev;
        num += hS[i] * ev;
    }
    redA[p][j] = den;
    redB[p][j] = num;
    __syncthreads();
    if (p == 0)
        vout[j] = (redB[0][j] + redB[1][j] + redB[2][j] + redB[3][j]) /
                  (redA[0][j] + redA[1][j] + redA[2][j] + redA[3][j]);
    __syncthreads();

    const float* wr = Wrec + ((size_t)e * 256 + tid) * 64;
    float acc = 0.f;
#pragma unroll 8
    for (int q = 0; q < 64; q++) acc = fmaf(vout[q], wr[q], acc);
    g_o[e][b][tid] = 1.f / (1.f + expf(-acc));
}

// ============================================================================
// K4: build gated split weights g_W5[b][ct][s][hi/lo][128][256]
// ============================================================================
__global__ void k4_w5(const float* __restrict__ Wqkv) {
    int b = blockIdx.x, ct = blockIdx.y, s = blockIdx.z;
    __shared__ float sA[128], sB[128];
    if (threadIdx.x < 128) {
        int c = ct * 128 + threadIdx.x;
        sA[threadIdx.x] = g_o[s][b][c] + g_o[s + 3][b][c] + g_o[s + 6][b][c];
        sB[threadIdx.x] = g_o[3 * s][b][c] + g_o[3 * s + 1][b][c] + g_o[3 * s + 2][b][c];
    }
    __syncthreads();
    const float* Wq = Wqkv + (size_t)(3 * s) * 65536 + (size_t)ct * 128 * 256;
    const float* Wk = Wq + 65536;
    const float* Wv = Wk + 65536;
    size_t base = (((size_t)(b * 2 + ct) * 3 + s) * 2) * 128 * 256;
    for (int i = threadIdx.x; i < 128 * 256; i += 256) {
        int row = i >> 8, cin = i & 255;
        float w = sA[row] * (Wq[row * 256 + cin] + Wv[row * 256 + cin])
                + sB[row] * Wk[row * 256 + cin];
        __half h, l;
        split_h(w, h, l);
        g_W5[base + i] = h;
        g_W5[base + 128 * 256 + i] = l;
    }
}

// ============================================================================
// K5: HMMA output GEMM (fp16 2-term: (Ah+Al)*Bh), accumulate 3 sources.
//     grid (2 ct, 4 b, 16 hz of 256 hw), block 256 (4m x 2n warps).
//     4 steps of 64 hw per s, double-buffered B hi plane.
// ============================================================================
__global__ void __launch_bounds__(256, 1)
k5_mma(float* __restrict__ out) {
    extern __shared__ __align__(16) char sm[];
    u32 smb = smem_u32(sm);

    int tid = threadIdx.x, wid = tid >> 5, lane = tid & 31;
    int ct = blockIdx.x, b = blockIdx.y, hz = blockIdx.z;

    int mwarp = wid >> 1, nwarp = wid & 1;
    int R0 = mwarp * 32;
    int H = nwarp * 32;

    u32 aoff = (u32)(R0 + (lane & 15)) * ROWB + (lane >> 4) * 16;
    u32 aHi = smb + aoff;
    u32 aLo = smb + SA_LO + aoff;
    u32 boff = (u32)(H + (lane & 7) + ((lane >= 16) ? 8 : 0)) * ROWB + ((lane & 8) ? 16 : 0);

    float acc[4][2][4][4] = {};   // [step][m][nt][4]

    // prologue: A(0) hi+lo, B(0, step0)
    {
        const __half* WA = g_W5 + (((size_t)(b * 2 + ct) * 3) * 2) * 128 * 256;
#pragma unroll
        for (int i = 0; i < 16; i++) {
            int f = tid + i * 256;
            int row = f >> 5, c = f & 31;
            size_t so = (size_t)row * 256 + c * 8;
            cp16(smb + row * ROWB + c * 16, WA + so);
            cp16(smb + SA_LO + row * ROWB + c * 16, WA + 128 * 256 + so);
        }
        CP_COMMIT();
        load_plane64(smb + K5_SMB, g_xT_hi + (size_t)b * 4096 * 256, hz * 256, tid);
        CP_COMMIT();
    }

    for (int s = 0; s < 3; s++) {
        const __half* XH = g_xT_hi + (size_t)(s * 4 + b) * 4096 * 256;

#pragma unroll
        for (int step = 0; step < 4; step++) {
            CP_WAIT0();         // A(s) + B(s,step) ready
            __syncthreads();

            if (step < 3) {
                load_plane64(smb + K5_SMB + ((step + 1) & 1) * BBUF, XH,
                             hz * 256 + (step + 1) * 64, tid);
                CP_COMMIT();
            }

            u32 bHi = smb + K5_SMB + (step & 1) * BBUF + boff;
#pragma unroll
            for (int kk = 0; kk < 16; kk++) {
                u32 kb = kk * 32;
                u32 ah0[4], ah1[4], al0[4], al1[4], bh0[4], bh1[4];
                ldsm4(ah0, aHi + kb);
                ldsm4(ah1, aHi + 16 * ROWB + kb);
                ldsm4(al0, aLo + kb);
                ldsm4(al1, aLo + 16 * ROWB + kb);
                ldsm4(bh0, bHi + kb);
                ldsm4(bh1, bHi + 16 * ROWB + kb);
#pragma unroll
                for (int m = 0; m < 2; m++) {
                    const u32* ah = m ? ah1 : ah0;
                    const u32* al = m ? al1 : al0;
                    mma16816(acc[step][m][0], ah, bh0);
                    mma16816(acc[step][m][0], al, bh0);
                    mma16816(acc[step][m][1], ah, bh0 + 2);
                    mma16816(acc[step][m][1], al, bh0 + 2);
                    mma16816(acc[step][m][2], ah, bh1);
                    mma16816(acc[step][m][2], al, bh1);
                    mma16816(acc[step][m][3], ah, bh1 + 2);
                    mma16816(acc[step][m][3], al, bh1 + 2);
                }
            }
            __syncthreads();    // everyone done reading A(s) / B(step)

            if (step == 3 && s < 2) {
                const __half* WA = g_W5 + (((size_t)(b * 2 + ct) * 3 + (s + 1)) * 2) * 128 * 256;
#pragma unroll
                for (int i = 0; i < 16; i++) {
                    int f = tid + i * 256;
                    int row = f >> 5, c = f & 31;
                    size_t so = (size_t)row * 256 + c * 8;
                    cp16(smb + row * ROWB + c * 16, WA + so);
                    cp16(smb + SA_LO + row * ROWB + c * 16, WA + 128 * 256 + so);
                }
                CP_COMMIT();
                load_plane64(smb + K5_SMB, g_xT_hi + (size_t)((s + 1) * 4 + b) * 4096 * 256,
                             hz * 256, tid);
                CP_COMMIT();
            }
        }
    }

    // store
    int g = lane >> 2, t = lane & 3;
#pragma unroll
    for (int step = 0; step < 4; step++)
#pragma unroll
        for (int m = 0; m < 2; m++)
#pragma unroll
            for (int nt = 0; nt < 4; nt++) {
                int ch = ct * 128 + R0 + m * 16 + g;
                int col = hz * 256 + step * 64 + H + nt * 8 + 2 * t;
                float2* p0 = (float2*)(out + ((size_t)b * NC + ch) * NHW + col);
                float2* p1 = (float2*)(out + ((size_t)b * NC + ch + 8) * NHW + col);
                *p0 = make_float2(acc[step][m][nt][0], acc[step][m][nt][1]);
                *p1 = make_float2(acc[step][m][nt][2], acc[step][m][nt][3]);
            }
}

// ============================================================================
extern "C" void kernel_launch(void* const* d_in, const int* in_sizes, int n_in,
                              void* d_out, int out_size) {
    (void)in_sizes; (void)n_in; (void)out_size;
    const float* t    = (const float*)d_in[0];
    const float* bb   = (const float*)d_in[1];
    const float* mm   = (const float*)d_in[2];
    const float* Wqkv = (const float*)d_in[3];
    const float* Wred = (const float*)d_in[4];
    const float* Wrec = (const float*)d_in[5];
    float* out = (float*)d_out;

    cudaFuncSetAttribute(k2_mma, cudaFuncAttributeMaxDynamicSharedMemorySize, K2_SMEM);
    cudaFuncSetAttribute(k5_mma, cudaFuncAttributeMaxDynamicSharedMemorySize, K5_SMEM);

    k0_split<<<dim3(12, 8, 16), 256>>>(t, bb, mm);
    k1_cm<<<dim3(27, 4), 256>>>(Wqkv, Wred);
    k2_mma<<<dim3(15, 4, 8), 256, K2_SMEM>>>();
    k3_attn<<<dim3(9, 4), 256>>>(Wrec);
    k4_w5<<<dim3(4, 2, 3), 256>>>(Wqkv);
    k5_mma<<<dim3(2, 4, 16), 256, K5_SMEM>>>(out);
}